// round 17
// baseline (speedup 1.0000x reference)
#include <cuda_runtime.h>
#include <cstdint>

#define Bn 64
#define Tn 512
#define In 128
#define Hn 512
#define TnHn (Tn*Hn)
#define BTH (64*512*512)

__device__ __forceinline__ uint32_t smem_u32(const void* p) {
    return (uint32_t)__cvta_generic_to_shared(p);
}
__device__ __forceinline__ void ffma2(unsigned long long& d,
                                      unsigned long long a,
                                      unsigned long long b) {
    asm("fma.rn.f32x2 %0, %1, %2, %0;" : "+l"(d) : "l"(a), "l"(b));
}
__device__ __forceinline__ float hsum2(unsigned long long a) {
    float lo, hi;
    asm("mov.b64 {%0, %1}, %2;" : "=f"(lo), "=f"(hi) : "l"(a));
    return lo + hi;
}
__device__ __forceinline__ void mbar_init(uint32_t mbar, uint32_t cnt) {
    asm volatile("mbarrier.init.shared.b64 [%0], %1;" :: "r"(mbar), "r"(cnt) : "memory");
}
__device__ __forceinline__ void mbar_expect_tx(uint32_t mbar, uint32_t bytes) {
    asm volatile("mbarrier.arrive.expect_tx.shared.b64 _, [%0], %1;"
                 :: "r"(mbar), "r"(bytes) : "memory");
}
__device__ __forceinline__ void mbar_wait(uint32_t mbar, uint32_t parity) {
    asm volatile(
        "{\n\t.reg .pred P;\n\t"
        "WL_%=:\n\t"
        "mbarrier.try_wait.parity.acquire.cta.shared::cta.b64 P, [%0], %1, 0x989680;\n\t"
        "@!P bra WL_%=;\n\t}"
        :: "r"(mbar), "r"(parity) : "memory");
}
__device__ __forceinline__ uint32_t mapa_rk(uint32_t la, int rk) {
    uint32_t ra;
    asm("mapa.shared::cluster.u32 %0, %1, %2;" : "=r"(ra) : "r"(la), "r"(rk));
    return ra;
}
__device__ __forceinline__ void bulk_cp(uint32_t dst, uint32_t src,
                                        uint32_t bytes, uint32_t rmbar) {
    asm volatile(
        "cp.async.bulk.shared::cluster.shared::cta.mbarrier::complete_tx::bytes "
        "[%0], [%1], %2, [%3];"
        :: "r"(dst), "r"(src), "r"(bytes), "r"(rmbar) : "memory");
}

// ---------------------------------------------------------------------------
// Fused recurrent kernel. 16 clusters x 8 CTAs x 512 thr (1 CTA/SM).
// Thread = (hl = tid>>3, seg = tid&7). W_hid row (rank*64+hl), cols
// [seg*64,+64) in 64 regs. One phase per t, all 4 cluster batches:
//   [stage x[t+1]: 1 LDG + 1 STS per thread] -> wait mbar -> rearm ->
//   jloop (64 LDS.128 + 128 FFMA2) -> 3x shfl_xor butterfly (8-lane groups)
//   -> replicated ew update (uses vin[t] regs) -> STS fresh block
//   -> __syncthreads -> 7x 1024-B bulk fan-out (threads 0..6)
//   -> TAIL FILLER before next wait: 1 STG output/thread + v_in[t+1]
//      compute from smem W_in + staged x (32 FFMA2 + LDS + 12 shfl).
// fr slots: [8 srcrank][4 b][64 h], 260-float block stride (one 128-B
// wavefront per jloop LDS.128 octet). tx per dest mbar per phase = 7168 B.
// Protocol/safety identical to R13 (proven correct): rearm->sync->bulks
// transitive gating, slot ping-pong WAR via read->bulk program order,
// trailing cluster barrier before exit.
// ---------------------------------------------------------------------------
#define BLKW   260
#define BLKB   1024u
#define SLOTF  (8*BLKW)            // 2080 floats
#define SLOTB  (SLOTF*4)           // 8320 B
#define WI_W   132
#define WI_F   (64*WI_W)           // W_in slice [64 h][132]
#define XS_W   132
#define XS_F   (2*4*XS_W)          // x stage [2 buf][4 b][132]
#define MB_OFF ((2*SLOTF + WI_F + XS_F)*4)
#define REC_SMEM (MB_OFF + 64)
#define TXB 7168u

struct RState {
    float v[4], vin[4];
    unsigned myot;
    int arr, b2;
};

template<bool SIG>
__device__ __forceinline__ void step_body(
    const float* __restrict__ rbase,   // read slot base
    float* __restrict__ wblk,          // my rank block in write slot
    uint32_t src_u,                    // same block, u32 addr
    const uint32_t* __restrict__ dsts, // 7 remote block addrs (write slot)
    const uint32_t* __restrict__ sigs, // 7 remote mbars (write slot)
    const ulonglong2* __restrict__ w,
    const float* __restrict__ Wi,      // W_in smem row base (hl*132)
    const float* __restrict__ xsb,     // x stage buf for t+1: [4 b][132]
    int seg, int hl, float al, float oma, float bias, float binv,
    RState& S, float* __restrict__ out, bool last)
{
    // ---- hidden GEMM over read slot ----
    const float* fb = rbase + seg*BLKW;
    unsigned long long ae[4] = {0ull,0ull,0ull,0ull};
    unsigned long long ao[4] = {0ull,0ull,0ull,0ull};
    #pragma unroll
    for (int i = 0; i < 16; i++) {
        const ulonglong2 wi = w[i];
        #pragma unroll
        for (int b = 0; b < 4; b++) {
            ulonglong2 f = *(const ulonglong2*)(fb + b*64 + i*4);
            ffma2(ae[b], wi.x, f.x);
            ffma2(ao[b], wi.y, f.y);
        }
    }
    float s0 = hsum2(ae[0]) + hsum2(ao[0]);
    float s1 = hsum2(ae[1]) + hsum2(ao[1]);
    float s2 = hsum2(ae[2]) + hsum2(ao[2]);
    float s3 = hsum2(ae[3]) + hsum2(ao[3]);
    #pragma unroll
    for (int m = 1; m < 8; m <<= 1) {
        s0 += __shfl_xor_sync(0xffffffffu, s0, m);
        s1 += __shfl_xor_sync(0xffffffffu, s1, m);
        s2 += __shfl_xor_sync(0xffffffffu, s2, m);
        s3 += __shfl_xor_sync(0xffffffffu, s3, m);
    }
    float vh[4] = { s0 + bias, s1 + bias, s2 + bias, s3 + bias };
    float fn[4], fr_r[4];
    #pragma unroll
    for (int b = 0; b < 4; b++) {
        float vn = oma*S.v[b] + al*(vh[b] + S.vin[b]);
        float vr = oma*vn + al*vh[b];
        S.v[b] = vn;
        fn[b]   = fmaxf(vn, 0.f);
        fr_r[b] = fmaxf(vr, 0.f);
    }

    if (SIG) {
        if (seg < 4) wblk[seg*64 + hl] = fn[seg];
        __syncthreads();
        if (threadIdx.x < 7) {
            asm volatile("fence.proxy.async.shared::cta;" ::: "memory");
            bulk_cp(dsts[threadIdx.x], src_u, BLKB, sigs[threadIdx.x]);
        }
    }

    // ---- tail filler (runs while bulks fly) ----
    out[S.myot] = S.arr ? fr_r[S.b2] : fn[S.b2];
    S.myot += Hn;

    if (!last) {
        // v_in[t+1] for 4 batches from staged x + smem W_in
        unsigned long long ve[4] = {0ull,0ull,0ull,0ull};
        #pragma unroll
        for (int k = 0; k < 4; k++) {
            ulonglong2 wv = *(const ulonglong2*)(Wi + seg*16 + k*4);
            #pragma unroll
            for (int b = 0; b < 4; b++) {
                ulonglong2 xv = *(const ulonglong2*)(xsb + b*XS_W + seg*16 + k*4);
                ffma2(ve[b], wv.x, xv.x);
                ffma2(ve[b], wv.y, xv.y);
            }
        }
        float t0 = hsum2(ve[0]), t1 = hsum2(ve[1]);
        float t2 = hsum2(ve[2]), t3 = hsum2(ve[3]);
        #pragma unroll
        for (int m = 1; m < 8; m <<= 1) {
            t0 += __shfl_xor_sync(0xffffffffu, t0, m);
            t1 += __shfl_xor_sync(0xffffffffu, t1, m);
            t2 += __shfl_xor_sync(0xffffffffu, t2, m);
            t3 += __shfl_xor_sync(0xffffffffu, t3, m);
        }
        S.vin[0] = t0 + binv; S.vin[1] = t1 + binv;
        S.vin[2] = t2 + binv; S.vin[3] = t3 + binv;
    }
}

__global__ __launch_bounds__(512, 1) __cluster_dims__(8, 1, 1)
void recur_kernel(const float* __restrict__ x,
                  const float* __restrict__ init_state,
                  const float* __restrict__ W_in,
                  const float* __restrict__ b_in,
                  const float* __restrict__ W_hid,
                  const float* __restrict__ b_hid,
                  const float* __restrict__ alpha,
                  float* __restrict__ out) {
    extern __shared__ float sm[];
    float* fr0 = sm;                   // [8 src][4 b][64] stride 260
    float* fr1 = sm + SLOTF;
    float* Wi  = sm + 2*SLOTF;         // [64 h][132]
    float* xs  = sm + 2*SLOTF + WI_F;  // [2][4 b][132]

    const int tid  = threadIdx.x;
    const int rank = blockIdx.x;
    const int clu  = blockIdx.y;
    const int hl   = tid >> 3;
    const int seg  = tid & 7;

    const uint32_t smb = smem_u32(sm);
    const uint32_t mb0 = smb + MB_OFF;
    const uint32_t mb1 = mb0 + 16;

    // ---- W_hid slice into regs ----
    ulonglong2 w[16];
    {
        const float* wr = W_hid + (size_t)(rank*64 + hl)*Hn + seg*64;
        #pragma unroll
        for (int i = 0; i < 16; i++)
            w[i] = *(const ulonglong2*)(wr + i*4);
    }

    // ---- W_in slice into smem: rows [rank*64,+64) x 128 i ----
    for (int idx = tid; idx < 64*128; idx += 512) {
        int r = idx >> 7, c = idx & 127;
        Wi[r*WI_W + c] = W_in[(size_t)(rank*64 + r)*In + c];
    }
    // ---- fr slot0 = relu(init_state) ----
    for (int idx = tid; idx < 2048; idx += 512) {
        int k = idx >> 8, b = (idx >> 6) & 3, i = idx & 63;
        float s = fmaxf(init_state[(size_t)(clu*4 + b)*Hn + k*64 + i], 0.f);
        fr0[k*BLKW + b*64 + i] = s;
    }
    // ---- stage x[0] into xs buf0 ----
    {
        int b = tid >> 7, i = tid & 127;
        xs[b*XS_W + i] = x[(size_t)(clu*4 + b)*Tn*In + 0*In + i];
    }

    if (tid == 0) {
        mbar_init(mb0, 1); mbar_init(mb1, 1);
        asm volatile("fence.mbarrier_init.release.cluster;" ::: "memory");
        mbar_expect_tx(mb0, TXB);
        mbar_expect_tx(mb1, TXB);
    }

    // ---- per-thread state ----
    const int hg = rank*64 + hl;
    const float al   = alpha[hg];
    const float oma  = 1.f - al;
    const float bias = b_hid[hg];
    const float binv = b_in[hg];
    RState S;
    S.arr = seg >> 2;
    S.b2  = seg & 3;
    #pragma unroll
    for (int b = 0; b < 4; b++)
        S.v[b] = init_state[(size_t)(clu*4 + b)*Hn + hg];
    S.myot = (unsigned)(S.arr*BTH) + (unsigned)((clu*4 + S.b2)*TnHn + hg);

    __syncthreads();

    // ---- vin[0] from staged x[0] (same math as tail filler) ----
    {
        unsigned long long ve[4] = {0ull,0ull,0ull,0ull};
        #pragma unroll
        for (int k = 0; k < 4; k++) {
            ulonglong2 wv = *(const ulonglong2*)(Wi + hl*WI_W + seg*16 + k*4);
            #pragma unroll
            for (int b = 0; b < 4; b++) {
                ulonglong2 xv = *(const ulonglong2*)(xs + b*XS_W + seg*16 + k*4);
                ffma2(ve[b], wv.x, xv.x);
                ffma2(ve[b], wv.y, xv.y);
            }
        }
        float t0 = hsum2(ve[0]), t1 = hsum2(ve[1]);
        float t2 = hsum2(ve[2]), t3 = hsum2(ve[3]);
        #pragma unroll
        for (int m = 1; m < 8; m <<= 1) {
            t0 += __shfl_xor_sync(0xffffffffu, t0, m);
            t1 += __shfl_xor_sync(0xffffffffu, t1, m);
            t2 += __shfl_xor_sync(0xffffffffu, t2, m);
            t3 += __shfl_xor_sync(0xffffffffu, t3, m);
        }
        S.vin[0] = t0 + binv; S.vin[1] = t1 + binv;
        S.vin[2] = t2 + binv; S.vin[3] = t3 + binv;
    }

    // ---- loop-invariant bulk targets ----
    const uint32_t myblk0_u = smb + (uint32_t)(rank*BLKW)*4u;
    const uint32_t myblk1_u = myblk0_u + SLOTB;
    uint32_t dst0[7], dst1[7], sg0[7], sg1[7];
    #pragma unroll
    for (int k = 0; k < 7; k++) {
        int dr = (rank + 1 + k) & 7;
        dst0[k] = mapa_rk(myblk0_u, dr);
        dst1[k] = mapa_rk(myblk1_u, dr);
        sg0[k]  = mapa_rk(mb0, dr);
        sg1[k]  = mapa_rk(mb1, dr);
    }
    float* wblk0 = fr0 + rank*BLKW;
    float* wblk1 = fr1 + rank*BLKW;
    const float* Wirow = Wi + hl*WI_W;

    // x-stage helper lambda-ish values
    const int xb = tid >> 7, xi = tid & 127;
    const float* xrow = x + (size_t)(clu*4 + xb)*Tn*In + xi;

    asm volatile("barrier.cluster.arrive.aligned;" ::: "memory");
    asm volatile("barrier.cluster.wait.aligned;"   ::: "memory");

    // ---- t = 0: stage x[1] into buf1, then step (read slot0 -> slot1) ----
    xs[XS_W*4 + xb*XS_W + xi] = __ldg(xrow + 1*In);
    step_body<true>(fr0, wblk1, myblk1_u, dst1, sg1, w, Wirow,
                    xs + XS_W*4, seg, hl, al, oma, bias, binv, S, out, false);

    // ---- steady state: t=2u+1 (slot1->0), t=2u+2 (slot0->1) ----
    #pragma unroll 1
    for (int u = 0; u < 255; ++u) {
        const uint32_t par = (uint32_t)(u & 1);
        const int t1 = 2*u + 1, t2 = 2*u + 2;

        // stage x[t1+1] into buf[(t1+1)&1] = buf0
        xs[xb*XS_W + xi] = __ldg(xrow + (size_t)(t1+1)*In);
        mbar_wait(mb1, par);
        if (tid == 0) mbar_expect_tx(mb1, TXB);
        step_body<true>(fr1, wblk0, myblk0_u, dst0, sg0, w, Wirow,
                        xs, seg, hl, al, oma, bias, binv, S, out, false);

        // stage x[t2+1] into buf[(t2+1)&1] = buf1 (t2+1 <= 512 -> clamp)
        {
            int tn = t2 + 1; if (tn > Tn - 1) tn = Tn - 1;
            xs[XS_W*4 + xb*XS_W + xi] = __ldg(xrow + (size_t)tn*In);
        }
        mbar_wait(mb0, par);
        if (tid == 0) mbar_expect_tx(mb0, TXB);
        step_body<true>(fr0, wblk1, myblk1_u, dst1, sg1, w, Wirow,
                        xs + XS_W*4, seg, hl, al, oma, bias, binv, S, out,
                        false);
    }

    // ---- t = 511: read slot1, no fan-out, no filler ----
    mbar_wait(mb1, 1u);
    step_body<false>(fr1, wblk0, myblk0_u, dst0, sg0, w, Wirow,
                     xs, seg, hl, al, oma, bias, binv, S, out, true);

    asm volatile("barrier.cluster.arrive.aligned;" ::: "memory");
    asm volatile("barrier.cluster.wait.aligned;"   ::: "memory");
}

// ---------------------------------------------------------------------------
extern "C" void kernel_launch(void* const* d_in, const int* in_sizes, int n_in,
                              void* d_out, int out_size) {
    const float* x          = (const float*)d_in[0];
    const float* init_state = (const float*)d_in[1];
    const float* W_in       = (const float*)d_in[2];
    const float* b_in       = (const float*)d_in[3];
    const float* W_hid      = (const float*)d_in[4];
    const float* b_hid      = (const float*)d_in[5];
    const float* alpha      = (const float*)d_in[6];
    float* out = (float*)d_out;

    cudaFuncSetAttribute(recur_kernel,
                         cudaFuncAttributeMaxDynamicSharedMemorySize, REC_SMEM);

    recur_kernel<<<dim3(8, Bn/4), 512, REC_SMEM>>>(x, init_state, W_in, b_in,
                                                   W_hid, b_hid, alpha, out);
}